// round 16
// baseline (speedup 1.0000x reference)
#include <cuda_runtime.h>
#include <cuda_fp16.h>
#include <cstdint>
#include <cstddef>

#define T_STEPS 512
#define DH      2048
#define DI      64
#define DO      64
#define BATCH   128
#define HC      64
#define NCHUNK  (DH / HC)        // 32
#define NB      64
#define USTR    72               // u32 stride (conflict-free: 72 mod 32 = 8)

// ---- device scratch ----
__device__ float    g_base[DH * BATCH];
__device__ float    g_part[4 * DH * BATCH];
__device__ unsigned g_win_h[NCHUNK * 2048];    // fp16x2 win A-frags [c][kt4][mt4][lane]
__device__ unsigned g_wout_h[NCHUNK * 2048];   // fp16x2 wout A-frags (K-permuted)
__device__ unsigned g_wfrag[4 * 32 * 32 * 4 * 32 * 4];
__device__ unsigned g_spk[1024 * 128];

__device__ __forceinline__ float sigm_exact(float x) {
    return __fdividef(1.0f, 1.0f + __expf(-x));
}
__device__ __forceinline__ float sigm(float x) {
    float t;
    asm("tanh.approx.f32 %0, %1;" : "=f"(t) : "f"(0.5f * x));
    return fmaf(0.5f, t, 0.5f);
}
__device__ __forceinline__ unsigned packh2(float a, float b) {
    __half2 h = __floats2half2_rn(a, b);   // a -> low half
    return *(unsigned*)&h;
}
__device__ __forceinline__ void mma_f16(float* c, uint4 a, unsigned b0, unsigned b1) {
    asm volatile("mma.sync.aligned.m16n8k16.row.col.f32.f16.f16.f32 "
                 "{%0,%1,%2,%3}, {%4,%5,%6,%7}, {%8,%9}, {%0,%1,%2,%3};"
                 : "+f"(c[0]), "+f"(c[1]), "+f"(c[2]), "+f"(c[3])
                 : "r"(a.x), "r"(a.y), "r"(a.z), "r"(a.w), "r"(b0), "r"(b1));
}

// ---------- kernel 1: packing (identical to R7 layouts, HC=64) ----------
__global__ void pack_all_kernel(const float* __restrict__ win,
                                const float* __restrict__ wout,
                                const float* __restrict__ r0,
                                const float* __restrict__ w_) {
    int bx = blockIdx.x;
    int tid = threadIdx.x;
    if (bx < 128) {
        int tg = (bx & 63) * 256 + tid;       // 0..16383
        int lane = tg & 31;
        int mt = (tg >> 5) & 3;
        int kt = (tg >> 7) & 3;
        int c  = tg >> 9;
        uint4 oh;
        if (bx < 64) {
            int r = (c * 4 + mt) * 16 + (lane >> 2);
            int k0 = kt * 16 + 2 * (lane & 3);
            oh.x = packh2(win[r * DI + k0],           win[r * DI + k0 + 1]);
            oh.y = packh2(win[(r + 8) * DI + k0],     win[(r + 8) * DI + k0 + 1]);
            oh.z = packh2(win[r * DI + k0 + 8],       win[r * DI + k0 + 9]);
            oh.w = packh2(win[(r + 8) * DI + k0 + 8], win[(r + 8) * DI + k0 + 9]);
            *(uint4*)(g_win_h + (size_t)tg * 4) = oh;
        } else {
            // wout: K-permuted so pair (2p,2p+1) <-> h = (Hp, Hp+8)
            int r = mt * 16 + (lane >> 2);
            int q3 = lane & 3;
            int h0 = c * HC + kt * 16 + q3;
            int h2 = h0 + 4;
            oh.x = packh2(wout[r * DH + h0],       wout[r * DH + h0 + 8]);
            oh.y = packh2(wout[(r + 8) * DH + h0], wout[(r + 8) * DH + h0 + 8]);
            oh.z = packh2(wout[r * DH + h2],       wout[r * DH + h2 + 8]);
            oh.w = packh2(wout[(r + 8) * DH + h2], wout[(r + 8) * DH + h2 + 8]);
            *(uint4*)(g_wout_h + (size_t)tg * 4) = oh;
        }
    } else if (bx < 384) {
        int i = (bx - 128) * 256 + tid;
        int bp = i & 63;
        int kp = i >> 6;
        float2 ra = *(const float2*)(r0 + (size_t)(2 * kp) * BATCH + 2 * bp);
        float2 rb = *(const float2*)(r0 + (size_t)(2 * kp + 1) * BATCH + 2 * bp);
        uint2 o;
        o.x = packh2(sigm_exact(ra.x), sigm_exact(rb.x));
        o.y = packh2(sigm_exact(ra.y), sigm_exact(rb.y));
        *(uint2*)(g_spk + (size_t)kp * BATCH + 2 * bp) = o;
    } else {
        int tg = (bx - 384) * 256 + tid;
        int lane = tg & 31;
        int mt = (tg >> 5) & 3;
        int kt = (tg >> 7) & 31;
        int hc = (tg >> 12) & 31;
        int kq = tg >> 17;
        int r  = hc * HC + mt * 16 + (lane >> 2);
        int k0 = kq * 512 + kt * 16 + 2 * (lane & 3);
        uint4 oh;
        oh.x = packh2(fabsf(w_[(size_t)r * DH + k0]),       fabsf(w_[(size_t)r * DH + k0 + 1]));
        oh.y = packh2(fabsf(w_[(size_t)(r + 8) * DH + k0]), fabsf(w_[(size_t)(r + 8) * DH + k0 + 1]));
        oh.z = packh2(fabsf(w_[(size_t)r * DH + k0 + 8]),   fabsf(w_[(size_t)r * DH + k0 + 9]));
        oh.w = packh2(fabsf(w_[(size_t)(r + 8) * DH + k0 + 8]), fabsf(w_[(size_t)(r + 8) * DH + k0 + 9]));
        *(uint4*)(g_wfrag + (size_t)tg * 4) = oh;
    }
}

// ---------- kernel 2: base GEMM partials ----------
__global__ void __launch_bounds__(256)
base_gemm_kernel() {
    int bx = blockIdx.x;
    int kq = bx >> 6;
    int hc = (bx >> 1) & 31;
    int nh = bx & 1;
    int tid  = threadIdx.x;
    int lane = tid & 31;
    int w    = tid >> 5;
    int qq   = lane & 3;
    int rr   = lane >> 2;
    int n    = nh * NB + w * 8 + rr;

    float C[4][4];
#pragma unroll
    for (int a = 0; a < 4; ++a)
#pragma unroll
        for (int q = 0; q < 4; ++q) C[a][q] = 0.0f;

    const uint4* Af = ((const uint4*)g_wfrag) + ((size_t)(kq * 32 + hc) * 32) * 128;
#pragma unroll 4
    for (int kt = 0; kt < 32; ++kt) {
        int kp = kq * 256 + kt * 8;
        unsigned b0 = g_spk[(size_t)(kp + qq) * BATCH + n];
        unsigned b1 = g_spk[(size_t)(kp + 4 + qq) * BATCH + n];
#pragma unroll
        for (int mt = 0; mt < 4; ++mt)
            mma_f16(C[mt], Af[(kt * 4 + mt) * 32 + lane], b0, b1);
    }
    float* dst = g_part + (size_t)kq * DH * BATCH;
    int n0 = nh * NB + w * 8 + 2 * qq;
#pragma unroll
    for (int mt = 0; mt < 4; ++mt)
#pragma unroll
        for (int hh = 0; hh < 2; ++hh) {
            int h = hc * HC + mt * 16 + hh * 8 + rr;
            *(float2*)(dst + (size_t)h * BATCH + n0) =
                make_float2(C[mt][hh * 2], C[mt][hh * 2 + 1]);
        }
}

// ---------- kernel 3: base reduce ----------
__global__ void base_reduce_kernel(const float* __restrict__ r0,
                                   const float* __restrict__ taus) {
    int i4 = (blockIdx.x * blockDim.x + threadIdx.x) * 4;
    int h  = i4 >> 7;
    float alpha = 1.0f / taus[h];
    float om = 1.0f - alpha;
    float4 rv = *(const float4*)(r0 + i4);
    float4 p0 = *(const float4*)(g_part + i4);
    float4 p1 = *(const float4*)(g_part + DH * BATCH + i4);
    float4 p2 = *(const float4*)(g_part + 2 * DH * BATCH + i4);
    float4 p3 = *(const float4*)(g_part + 3 * DH * BATCH + i4);
    float4 o;
    o.x = om * rv.x + alpha * (p0.x + p1.x + p2.x + p3.x);
    o.y = om * rv.y + alpha * (p0.y + p1.y + p2.y + p3.y);
    o.z = om * rv.z + alpha * (p0.z + p1.z + p2.z + p3.z);
    o.w = om * rv.w + alpha * (p0.w + p1.w + p2.w + p3.w);
    *(float4*)(g_base + i4) = o;
}

// ---------- kernel 4: main — 1 t per block, occupancy 3 ----------
// smem (u32): WINB[2] 0..4096 | WOUTB[2] 4096..8192 | UH 8192..10496 |
//             S[2] 10496..15104  (2304 each)
#define OFF_WOUT 4096
#define OFF_UH   8192
#define OFF_S    10496
#define SMEM_U32 15104

__global__ void __launch_bounds__(256, 3)
main_kernel(const float* __restrict__ u,
            const float* __restrict__ noise,
            const float* __restrict__ bias,
            float* __restrict__ out) {
    extern __shared__ unsigned smu[];
    unsigned* WINB  = smu;
    unsigned* WOUTB = smu + OFF_WOUT;
    unsigned* uh    = smu + OFF_UH;

    int tid  = threadIdx.x;
    int lane = tid & 31;
    int w    = tid >> 5;
    int qq   = lane & 3;
    int rr   = lane >> 2;

    int t  = blockIdx.x >> 1;
    int nb = (blockIdx.x & 1) * NB;

    float* xsout = out + (size_t)T_STEPS * DO * BATCH;

    // ---- prologue: stage u[t] slice (fp16 hi, k-pair) + win[0] + wout[0] ----
    {
        const float* ut = u + (size_t)t * DI * BATCH + nb;
#pragma unroll
        for (int i = 0; i < 4; ++i) {
            int idx = tid + i * 256;
            int dp  = idx >> 5;
            int b2  = (idx & 31) * 2;
            float2 ra = *(const float2*)(ut + (2 * dp) * BATCH + b2);
            float2 rb = *(const float2*)(ut + (2 * dp + 1) * BATCH + b2);
            *(uint2*)(uh + dp * USTR + b2) =
                make_uint2(packh2(ra.x, rb.x), packh2(ra.y, rb.y));
        }
    }
    ((uint4*)WINB)[tid]        = ((const uint4*)g_win_h)[tid];
    ((uint4*)WINB)[tid + 256]  = ((const uint4*)g_win_h)[tid + 256];
    ((uint4*)WOUTB)[tid]       = ((const uint4*)g_wout_h)[tid];
    ((uint4*)WOUTB)[tid + 256] = ((const uint4*)g_wout_h)[tid + 256];

    float C2[4][4];
#pragma unroll
    for (int a = 0; a < 4; ++a)
#pragma unroll
        for (int q = 0; q < 4; ++q) C2[a][q] = 0.0f;

    int n0 = nb + w * 8 + 2 * qq;     // global batch col (pair base)
    int nl = w * 8 + 2 * qq;          // local batch col
    int n  = w * 8 + rr;              // B-fragment col

    __syncthreads();

    for (int c = 0; c < NCHUNK; ++c) {
        // ---- prefetch noise for this chunk (DRAM; covered by GEMM1) ----
        float2 nz[8];
#pragma unroll
        for (int mt = 0; mt < 4; ++mt)
#pragma unroll
            for (int hh = 0; hh < 2; ++hh) {
                int hg = c * HC + mt * 16 + hh * 8 + rr;
                nz[mt * 2 + hh] = *(const float2*)(noise + ((size_t)t * DH + hg) * BATCH + n0);
            }

        // ---- stage win[c+1] ----
        if (c + 1 < NCHUNK) {
            uint4* dst = (uint4*)(WINB + ((c + 1) & 1) * 2048);
            const uint4* src = ((const uint4*)g_win_h) + (size_t)(c + 1) * 512;
            dst[tid]       = src[tid];
            dst[tid + 256] = src[tid + 256];
        }

        // ---- GEMM1: inp = win_h @ u_h ----
        const unsigned* A1 = WINB + (c & 1) * 2048;
        float C1[4][4];
#pragma unroll
        for (int a = 0; a < 4; ++a)
#pragma unroll
            for (int q = 0; q < 4; ++q) C1[a][q] = 0.0f;

#pragma unroll
        for (int kt = 0; kt < 4; ++kt) {
            unsigned b0 = uh[(kt * 8 + qq) * USTR + n];
            unsigned b1 = uh[(kt * 8 + 4 + qq) * USTR + n];
#pragma unroll
            for (int mt = 0; mt < 4; ++mt) {
                uint4 a4 = *(const uint4*)(A1 + ((kt * 4 + mt) * 32 + lane) * 4);
                mma_f16(C1[mt], a4, b0, b1);
            }
        }

        // ---- batched base loads (L2-resident) ----
        float2 bs[8];
#pragma unroll
        for (int mt = 0; mt < 4; ++mt)
#pragma unroll
            for (int hh = 0; hh < 2; ++hh) {
                int hg = c * HC + mt * 16 + hh * 8 + rr;
                bs[mt * 2 + hh] = *(const float2*)(g_base + (size_t)hg * BATCH + n0);
            }

        // ---- epilogue: xs out + S (pair-permuted, STS.64) ----
        unsigned* S0 = smu + OFF_S + (c & 1) * 2304;
#pragma unroll
        for (int mt = 0; mt < 4; ++mt) {
            int hg0 = c * HC + mt * 16 + rr;
            float2 nn0 = nz[mt * 2], nn1 = nz[mt * 2 + 1];
            float2 bb0 = bs[mt * 2], bb1 = bs[mt * 2 + 1];
            float xa0 = C1[mt][0] + nn0.x + bb0.x;
            float xa1 = C1[mt][1] + nn0.y + bb0.y;
            float xb0 = C1[mt][2] + nn1.x + bb1.x;
            float xb1 = C1[mt][3] + nn1.y + bb1.y;
            *(float2*)(xsout + ((size_t)t * DH + hg0) * BATCH + n0)     = make_float2(xa0, xa1);
            *(float2*)(xsout + ((size_t)t * DH + hg0 + 8) * BATCH + n0) = make_float2(xb0, xb1);
            uint2 sw;
            sw.x = packh2(sigm(xa0), sigm(xb0));
            sw.y = packh2(sigm(xa1), sigm(xb1));
            *(uint2*)(S0 + (mt * 8 + rr) * USTR + nl) = sw;
        }
        __syncthreads();   // the one sync per chunk

        // ---- stage wout[c+1] ----
        if (c + 1 < NCHUNK) {
            uint4* dst = (uint4*)(WOUTB + ((c + 1) & 1) * 2048);
            const uint4* src = ((const uint4*)g_wout_h) + (size_t)(c + 1) * 512;
            dst[tid]       = src[tid];
            dst[tid + 256] = src[tid + 256];
        }

        // ---- GEMM2: out += wout_h @ s (permuted K) ----
        const unsigned* A2  = WOUTB + (c & 1) * 2048;
        const unsigned* S0r = smu + OFF_S + (c & 1) * 2304;
#pragma unroll
        for (int kt = 0; kt < 4; ++kt) {
            unsigned s0 = S0r[(kt * 8 + qq) * USTR + n];
            unsigned s1 = S0r[(kt * 8 + 4 + qq) * USTR + n];
#pragma unroll
            for (int mt = 0; mt < 4; ++mt) {
                uint4 a4 = *(const uint4*)(A2 + ((kt * 4 + mt) * 32 + lane) * 4);
                mma_f16(C2[mt], a4, s0, s1);
            }
        }
    }

    // ---- write outputs[t] ----
#pragma unroll
    for (int mt = 0; mt < 4; ++mt) {
        int o0 = mt * 16 + rr;
        float bv0 = __ldg(bias + o0);
        float bv8 = __ldg(bias + o0 + 8);
        *(float2*)(out + ((size_t)t * DO + o0) * BATCH + n0) =
            make_float2(C2[mt][0] + bv0, C2[mt][1] + bv0);
        *(float2*)(out + ((size_t)t * DO + o0 + 8) * BATCH + n0) =
            make_float2(C2[mt][2] + bv8, C2[mt][3] + bv8);
    }
}

extern "C" void kernel_launch(void* const* d_in, const int* in_sizes, int n_in,
                              void* d_out, int out_size) {
    const float* u     = (const float*)d_in[0];
    const float* r0    = (const float*)d_in[1];
    const float* noise = (const float*)d_in[2];
    const float* win   = (const float*)d_in[3];
    const float* w_    = (const float*)d_in[4];
    // d_in[5] = m_diag: unused — |_w * (+-1)| == |_w|
    const float* wout  = (const float*)d_in[6];
    const float* bias  = (const float*)d_in[7];
    const float* taus  = (const float*)d_in[8];
    float* out = (float*)d_out;

    const int main_smem = SMEM_U32 * 4;   // 60416 B -> 3 blocks/SM
    cudaFuncSetAttribute(main_kernel, cudaFuncAttributeMaxDynamicSharedMemorySize, main_smem);

    pack_all_kernel<<<2432, 256>>>(win, wout, r0, w_);
    base_gemm_kernel<<<256, 256>>>();
    base_reduce_kernel<<<256, 256>>>(r0, taus);
    main_kernel<<<2 * T_STEPS, 256, main_smem>>>(u, noise, bias, out);
}

// round 17
// speedup vs baseline: 1.2967x; 1.2967x over previous
#include <cuda_runtime.h>
#include <cuda_fp16.h>
#include <cstdint>
#include <cstddef>

#define T_STEPS 512
#define DH      2048
#define DI      64
#define DO      64
#define BATCH   128
#define HC      64
#define NCHUNK  (DH / HC)        // 32
#define NB      64
#define USTR    72               // u32/float stride (conflict-free)

// ---- device scratch ----
__device__ float    g_base[DH * BATCH];
__device__ float    g_part[4 * DH * BATCH];
__device__ unsigned g_win_h[65536];    // [ht128][kt4][lane] uint4 frags
__device__ unsigned g_wout_h[65536];   // [c32][kt4][mt4][lane] uint4 frags (natural K)
__device__ unsigned g_wfrag[4 * 32 * 32 * 4 * 32 * 4];
__device__ unsigned g_spk[1024 * 128];

__device__ __forceinline__ float sigm_exact(float x) {
    return __fdividef(1.0f, 1.0f + __expf(-x));
}
__device__ __forceinline__ float sigm(float x) {
    float t;
    asm("tanh.approx.f32 %0, %1;" : "=f"(t) : "f"(0.5f * x));
    return fmaf(0.5f, t, 0.5f);
}
__device__ __forceinline__ unsigned packh2(float a, float b) {
    __half2 h = __floats2half2_rn(a, b);   // a -> low half
    return *(unsigned*)&h;
}
__device__ __forceinline__ void mma_f16(float* c, uint4 a, unsigned b0, unsigned b1) {
    asm volatile("mma.sync.aligned.m16n8k16.row.col.f32.f16.f16.f32 "
                 "{%0,%1,%2,%3}, {%4,%5,%6,%7}, {%8,%9}, {%0,%1,%2,%3};"
                 : "+f"(c[0]), "+f"(c[1]), "+f"(c[2]), "+f"(c[3])
                 : "r"(a.x), "r"(a.y), "r"(a.z), "r"(a.w), "r"(b0), "r"(b1));
}

// ---------- kernel 1: packing ----------
__global__ void pack_all_kernel(const float* __restrict__ win,
                                const float* __restrict__ wout,
                                const float* __restrict__ r0,
                                const float* __restrict__ w_) {
    int bx = blockIdx.x;
    int tid = threadIdx.x;
    if (bx < 128) {
        int tg = (bx & 63) * 256 + tid;       // 0..16383
        int lane = tg & 31;
        uint4 oh;
        if (bx < 64) {
            // win: [ht][kt][lane]
            int kt = (tg >> 5) & 3;
            int ht = tg >> 7;                  // 0..127
            int r  = ht * 16 + (lane >> 2);
            int k0 = kt * 16 + 2 * (lane & 3);
            oh.x = packh2(win[r * DI + k0],           win[r * DI + k0 + 1]);
            oh.y = packh2(win[(r + 8) * DI + k0],     win[(r + 8) * DI + k0 + 1]);
            oh.z = packh2(win[r * DI + k0 + 8],       win[r * DI + k0 + 9]);
            oh.w = packh2(win[(r + 8) * DI + k0 + 8], win[(r + 8) * DI + k0 + 9]);
            *(uint4*)(g_win_h + (size_t)tg * 4) = oh;
        } else {
            // wout natural K, chunk=64: [c32][kt4][mt4][lane]
            int mt = (tg >> 5) & 3;
            int kt = (tg >> 7) & 3;
            int c  = tg >> 9;                  // 0..31
            int r  = mt * 16 + (lane >> 2);
            int k0 = c * HC + kt * 16 + 2 * (lane & 3);
            oh.x = packh2(wout[r * DH + k0],           wout[r * DH + k0 + 1]);
            oh.y = packh2(wout[(r + 8) * DH + k0],     wout[(r + 8) * DH + k0 + 1]);
            oh.z = packh2(wout[r * DH + k0 + 8],       wout[r * DH + k0 + 9]);
            oh.w = packh2(wout[(r + 8) * DH + k0 + 8], wout[(r + 8) * DH + k0 + 9]);
            *(uint4*)(g_wout_h + (size_t)tg * 4) = oh;
        }
    } else if (bx < 384) {
        int i = (bx - 128) * 256 + tid;
        int bp = i & 63;
        int kp = i >> 6;
        float2 ra = *(const float2*)(r0 + (size_t)(2 * kp) * BATCH + 2 * bp);
        float2 rb = *(const float2*)(r0 + (size_t)(2 * kp + 1) * BATCH + 2 * bp);
        uint2 o;
        o.x = packh2(sigm_exact(ra.x), sigm_exact(rb.x));
        o.y = packh2(sigm_exact(ra.y), sigm_exact(rb.y));
        *(uint2*)(g_spk + (size_t)kp * BATCH + 2 * bp) = o;
    } else {
        int tg = (bx - 384) * 256 + tid;
        int lane = tg & 31;
        int mt = (tg >> 5) & 3;
        int kt = (tg >> 7) & 31;
        int hc = (tg >> 12) & 31;
        int kq = tg >> 17;
        int r  = hc * 64 + mt * 16 + (lane >> 2);
        int k0 = kq * 512 + kt * 16 + 2 * (lane & 3);
        uint4 oh;
        oh.x = packh2(fabsf(w_[(size_t)r * DH + k0]),       fabsf(w_[(size_t)r * DH + k0 + 1]));
        oh.y = packh2(fabsf(w_[(size_t)(r + 8) * DH + k0]), fabsf(w_[(size_t)(r + 8) * DH + k0 + 1]));
        oh.z = packh2(fabsf(w_[(size_t)r * DH + k0 + 8]),   fabsf(w_[(size_t)r * DH + k0 + 9]));
        oh.w = packh2(fabsf(w_[(size_t)(r + 8) * DH + k0 + 8]), fabsf(w_[(size_t)(r + 8) * DH + k0 + 9]));
        *(uint4*)(g_wfrag + (size_t)tg * 4) = oh;
    }
}

// ---------- kernel 2: base GEMM partials ----------
__global__ void __launch_bounds__(256)
base_gemm_kernel() {
    int bx = blockIdx.x;
    int kq = bx >> 6;
    int hc = (bx >> 1) & 31;
    int nh = bx & 1;
    int tid  = threadIdx.x;
    int lane = tid & 31;
    int w    = tid >> 5;
    int qq   = lane & 3;
    int rr   = lane >> 2;
    int n    = nh * NB + w * 8 + rr;

    float C[4][4];
#pragma unroll
    for (int a = 0; a < 4; ++a)
#pragma unroll
        for (int q = 0; q < 4; ++q) C[a][q] = 0.0f;

    const uint4* Af = ((const uint4*)g_wfrag) + ((size_t)(kq * 32 + hc) * 32) * 128;
#pragma unroll 4
    for (int kt = 0; kt < 32; ++kt) {
        int kp = kq * 256 + kt * 8;
        unsigned b0 = g_spk[(size_t)(kp + qq) * BATCH + n];
        unsigned b1 = g_spk[(size_t)(kp + 4 + qq) * BATCH + n];
#pragma unroll
        for (int mt = 0; mt < 4; ++mt)
            mma_f16(C[mt], Af[(kt * 4 + mt) * 32 + lane], b0, b1);
    }
    float* dst = g_part + (size_t)kq * DH * BATCH;
    int n0 = nh * NB + w * 8 + 2 * qq;
#pragma unroll
    for (int mt = 0; mt < 4; ++mt)
#pragma unroll
        for (int hh = 0; hh < 2; ++hh) {
            int h = hc * 64 + mt * 16 + hh * 8 + rr;
            *(float2*)(dst + (size_t)h * BATCH + n0) =
                make_float2(C[mt][hh * 2], C[mt][hh * 2 + 1]);
        }
}

// ---------- kernel 3: base reduce ----------
__global__ void base_reduce_kernel(const float* __restrict__ r0,
                                   const float* __restrict__ taus) {
    int i4 = (blockIdx.x * blockDim.x + threadIdx.x) * 4;
    int h  = i4 >> 7;
    float alpha = 1.0f / taus[h];
    float om = 1.0f - alpha;
    float4 rv = *(const float4*)(r0 + i4);
    float4 p0 = *(const float4*)(g_part + i4);
    float4 p1 = *(const float4*)(g_part + DH * BATCH + i4);
    float4 p2 = *(const float4*)(g_part + 2 * DH * BATCH + i4);
    float4 p3 = *(const float4*)(g_part + 3 * DH * BATCH + i4);
    float4 o;
    o.x = om * rv.x + alpha * (p0.x + p1.x + p2.x + p3.x);
    o.y = om * rv.y + alpha * (p0.y + p1.y + p2.y + p3.y);
    o.z = om * rv.z + alpha * (p0.z + p1.z + p2.z + p3.z);
    o.w = om * rv.w + alpha * (p0.w + p1.w + p2.w + p3.w);
    *(float4*)(g_base + i4) = o;
}

// ---------- kernel 4: main — 2t per block, warp-group t-split ----------
// smem (u32): u[2t] 0..4608 (2304 each) | T 4608..13824 (warp-private 1152 each) |
//             S[2t][2buf] 13824..23040 (2304 each)
#define oU 0
#define oT 4608
#define oS 13824
#define SMEM_U32 23040

__global__ void __launch_bounds__(256, 2)
main_kernel(const float* __restrict__ u,
            const float* __restrict__ noise,
            const float* __restrict__ bias,
            float* __restrict__ out) {
    extern __shared__ unsigned smu[];

    int tid  = threadIdx.x;
    int lane = tid & 31;
    int w    = tid >> 5;
    int wg   = w >> 2;            // t-group 0/1
    int wl   = w & 3;             // warp within group: 16h slice
    int qq   = lane & 3;
    int rr   = lane >> 2;

    int t0 = (blockIdx.x >> 1) * 2;
    int t  = t0 + wg;
    int nb = (blockIdx.x & 1) * NB;
    int gb = nb + 2 * lane;

    float* xsout = out + (size_t)T_STEPS * DO * BATCH;

    // ---- prologue: stage u[t0], u[t1] (fp16, k-pair layout) ----
#pragma unroll
    for (int tt = 0; tt < 2; ++tt) {
        const float* ut = u + (size_t)(t0 + tt) * DI * BATCH + nb;
        unsigned* dst = smu + oU + tt * 2304;
#pragma unroll
        for (int i = 0; i < 4; ++i) {
            int idx = tid + i * 256;
            int dp  = idx >> 5;
            int b2  = (idx & 31) * 2;
            float2 ra = *(const float2*)(ut + (2 * dp) * BATCH + b2);
            float2 rb = *(const float2*)(ut + (2 * dp + 1) * BATCH + b2);
            *(uint2*)(dst + dp * USTR + b2) =
                make_uint2(packh2(ra.x, rb.x), packh2(ra.y, rb.y));
        }
    }

    const unsigned* uT = smu + oU + wg * 2304;
    float* Tw = (float*)(smu + oT) + w * (16 * USTR);
    unsigned* Sgrp = smu + oS + wg * 2 * 2304;

    float C2[4][2][4];
#pragma unroll
    for (int a = 0; a < 4; ++a)
#pragma unroll
        for (int b = 0; b < 2; ++b)
#pragma unroll
            for (int q = 0; q < 4; ++q) C2[a][b][q] = 0.0f;

    // noise/base rings: pairs 0,1 of chunk 0
    float2 pnz[2][2], pbs[2][2];
#pragma unroll
    for (int s = 0; s < 2; ++s) {
        int h0 = wl * 16 + 2 * s;
        pnz[s][0] = *(const float2*)(noise + ((size_t)t * DH + h0) * BATCH + gb);
        pnz[s][1] = *(const float2*)(noise + ((size_t)t * DH + h0 + 1) * BATCH + gb);
        pbs[s][0] = *(const float2*)(g_base + (size_t)h0 * BATCH + gb);
        pbs[s][1] = *(const float2*)(g_base + (size_t)(h0 + 1) * BATCH + gb);
    }

    __syncthreads();   // u staged (only block-wide sync)

    for (int c = 0; c < NCHUNK; ++c) {
        // ---- GEMM1: 16h x 64n tile for this warp's t ----
        uint4 A1[4];
#pragma unroll
        for (int kt = 0; kt < 4; ++kt)
            A1[kt] = ((const uint4*)g_win_h)[((c * 4 + wl) * 4 + kt) * 32 + lane];

        float C1[8][4];
#pragma unroll
        for (int a = 0; a < 8; ++a)
#pragma unroll
            for (int q = 0; q < 4; ++q) C1[a][q] = 0.0f;
#pragma unroll
        for (int kt = 0; kt < 4; ++kt) {
#pragma unroll
            for (int nt = 0; nt < 8; ++nt) {
                unsigned b0 = uT[(kt * 8 + qq) * USTR + nt * 8 + rr];
                unsigned b1 = uT[(kt * 8 + 4 + qq) * USTR + nt * 8 + rr];
                mma_f16(C1[nt], A1[kt], b0, b1);
            }
        }

        // ---- warp-private transpose ----
#pragma unroll
        for (int nt = 0; nt < 8; ++nt) {
            int col = nt * 8 + 2 * qq;
            *(float2*)(Tw + rr * USTR + col)       = make_float2(C1[nt][0], C1[nt][1]);
            *(float2*)(Tw + (rr + 8) * USTR + col) = make_float2(C1[nt][2], C1[nt][3]);
        }
        __syncwarp();

        // ---- epilogue: coalesced, 8 row-pairs ----
        unsigned* S0 = Sgrp + (c & 1) * 2304;
        int R0c = c * HC + wl * 16;
#pragma unroll
        for (int p = 0; p < 8; ++p) {
            int sl = p & 1;
            float2 xr0 = *(const float2*)(Tw + (2 * p) * USTR + 2 * lane);
            float2 xr1 = *(const float2*)(Tw + (2 * p + 1) * USTR + 2 * lane);
            float x00 = xr0.x + pnz[sl][0].x + pbs[sl][0].x;
            float x01 = xr0.y + pnz[sl][0].y + pbs[sl][0].y;
            float x10 = xr1.x + pnz[sl][1].x + pbs[sl][1].x;
            float x11 = xr1.y + pnz[sl][1].y + pbs[sl][1].y;
            size_t gx = ((size_t)t * DH + R0c + 2 * p) * BATCH + gb;
            *(float2*)(xsout + gx)         = make_float2(x00, x01);
            *(float2*)(xsout + gx + BATCH) = make_float2(x10, x11);
            *(uint2*)(S0 + (wl * 8 + p) * USTR + 2 * lane) =
                make_uint2(packh2(sigm(x00), sigm(x10)),
                           packh2(sigm(x01), sigm(x11)));
            int pg = p + 2;
            if (pg < 8 || c < NCHUNK - 1) {
                int hld = (pg < 8) ? (R0c + 2 * pg) : (R0c + HC + 2 * (pg - 8));
                pnz[sl][0] = *(const float2*)(noise + ((size_t)t * DH + hld) * BATCH + gb);
                pnz[sl][1] = *(const float2*)(noise + ((size_t)t * DH + hld + 1) * BATCH + gb);
                pbs[sl][0] = *(const float2*)(g_base + (size_t)hld * BATCH + gb);
                pbs[sl][1] = *(const float2*)(g_base + (size_t)(hld + 1) * BATCH + gb);
            }
        }

        // group barrier: S complete for this t-group
        asm volatile("bar.sync %0, %1;" :: "r"(1 + wg), "r"(128) : "memory");

        // ---- GEMM2: C2 += wout_chunk @ S (natural pairs), prefetched A ----
        const uint4* W2 = ((const uint4*)g_wout_h) + (size_t)(c * 16) * 32;
        uint4 a4[4];
#pragma unroll
        for (int mt = 0; mt < 4; ++mt) a4[mt] = W2[mt * 32 + lane];
#pragma unroll
        for (int kt = 0; kt < 4; ++kt) {
            uint4 nx[4];
            if (kt < 3) {
#pragma unroll
                for (int mt = 0; mt < 4; ++mt)
                    nx[mt] = W2[((kt + 1) * 4 + mt) * 32 + lane];
            }
#pragma unroll
            for (int nt = 0; nt < 2; ++nt) {
                unsigned s0 = S0[(kt * 8 + qq) * USTR + wl * 16 + nt * 8 + rr];
                unsigned s1 = S0[(kt * 8 + 4 + qq) * USTR + wl * 16 + nt * 8 + rr];
#pragma unroll
                for (int mt = 0; mt < 4; ++mt)
                    mma_f16(C2[mt][nt], a4[mt], s0, s1);
            }
#pragma unroll
            for (int mt = 0; mt < 4; ++mt) a4[mt] = nx[mt];
        }
    }

    // ---- write outputs[t] ----
#pragma unroll
    for (int mt = 0; mt < 4; ++mt) {
#pragma unroll
        for (int nt = 0; nt < 2; ++nt) {
            int o0 = mt * 16 + rr;
            int nc = nb + wl * 16 + nt * 8 + 2 * qq;
            float bv0 = __ldg(bias + o0);
            float bv8 = __ldg(bias + o0 + 8);
            *(float2*)(out + ((size_t)t * DO + o0) * BATCH + nc) =
                make_float2(C2[mt][nt][0] + bv0, C2[mt][nt][1] + bv0);
            *(float2*)(out + ((size_t)t * DO + o0 + 8) * BATCH + nc) =
                make_float2(C2[mt][nt][2] + bv8, C2[mt][nt][3] + bv8);
        }
    }
}

extern "C" void kernel_launch(void* const* d_in, const int* in_sizes, int n_in,
                              void* d_out, int out_size) {
    const float* u     = (const float*)d_in[0];
    const float* r0    = (const float*)d_in[1];
    const float* noise = (const float*)d_in[2];
    const float* win   = (const float*)d_in[3];
    const float* w_    = (const float*)d_in[4];
    // d_in[5] = m_diag: unused — |_w * (+-1)| == |_w|
    const float* wout  = (const float*)d_in[6];
    const float* bias  = (const float*)d_in[7];
    const float* taus  = (const float*)d_in[8];
    float* out = (float*)d_out;

    const int main_smem = SMEM_U32 * 4;   // 92160 B -> 2 blocks/SM
    cudaFuncSetAttribute(main_kernel, cudaFuncAttributeMaxDynamicSharedMemorySize, main_smem);

    pack_all_kernel<<<2432, 256>>>(win, wout, r0, w_);
    base_gemm_kernel<<<256, 256>>>();
    base_reduce_kernel<<<256, 256>>>(r0, taus);
    main_kernel<<<T_STEPS, 256, main_smem>>>(u, noise, bias, out);
}